// round 3
// baseline (speedup 1.0000x reference)
#include <cuda_runtime.h>
#include <cstdint>

#define N_NODES   100000
#define N_EDGES   1600000
#define FEAT_DIM  128
#define EMBED_DIM 32
#define NC        17
#define A_STRIDE  24   // 96B rows: 3 sectors exactly, 16B aligned
#define R_STRIDE  20   // 80B rows: 16B aligned for red.v4

// -------- device scratch (allocation-free rule: static __device__ globals) ---
__device__ __align__(16) float g_embed[N_NODES * EMBED_DIM];   // 12.8 MB
__device__ __align__(16) float g_A[N_NODES * A_STRIDE];        //  9.6 MB
__device__ __align__(16) float g_recall[N_NODES * R_STRIDE];   //  8.0 MB

// -------- f32x2 packed helpers ----------------------------------------------
__device__ __forceinline__ unsigned long long pk2(float lo, float hi) {
    unsigned long long r;
    asm("mov.b64 %0, {%1,%2};" : "=l"(r) : "f"(lo), "f"(hi));
    return r;
}
__device__ __forceinline__ void upk2(unsigned long long v, float& lo, float& hi) {
    asm("mov.b64 {%0,%1}, %2;" : "=f"(lo), "=f"(hi) : "l"(v));
}
__device__ __forceinline__ unsigned long long fma2(unsigned long long a,
                                                   unsigned long long b,
                                                   unsigned long long c) {
    unsigned long long d;
    asm("fma.rn.f32x2 %0, %1, %2, %3;" : "=l"(d) : "l"(a), "l"(b), "l"(c));
    return d;
}

// ============================================================================
// Kernel A: embed = feat @ W_embed + b_embed ;  A[n] = 0.5 e^T W1 + (e*e)^T W2
// one warp per node, 8 nodes per 256-thread block
// ============================================================================
__global__ __launch_bounds__(256) void node_kernel(
    const float* __restrict__ feat, const float* __restrict__ Wemb,
    const float* __restrict__ bemb, const float* __restrict__ Wtr)
{
    __shared__ __align__(16) float sW[FEAT_DIM * EMBED_DIM];   // 16 KB, [k][j]
    __shared__ float sW1h[EMBED_DIM][NC];        // 0.5 * W_trans[0:32]
    __shared__ float sW2[EMBED_DIM][NC];         //       W_trans[32:64]
    __shared__ __align__(16) float sFeat[8][FEAT_DIM];
    __shared__ float sE[8][EMBED_DIM];

    const int t = threadIdx.x;
    {
        const float4* W4  = (const float4*)Wemb;
        float4*       sW4 = (float4*)sW;
        #pragma unroll
        for (int i = t; i < FEAT_DIM * EMBED_DIM / 4; i += 256) sW4[i] = W4[i];
        for (int i = t; i < EMBED_DIM * NC; i += 256) {
            int k = i / NC, c = i - k * NC;
            sW1h[k][c] = 0.5f * Wtr[k * NC + c];
            sW2[k][c]  = Wtr[(EMBED_DIM + k) * NC + c];
        }
    }
    __syncthreads();

    const int w = t >> 5, lane = t & 31;
    const int n = blockIdx.x * 8 + w;

    // cooperative feat load: 128 floats = 32 lanes x float4
    ((float4*)sFeat[w])[lane] = ((const float4*)(feat + (size_t)n * FEAT_DIM))[lane];
    __syncwarp();

    float acc = bemb[lane];
    #pragma unroll
    for (int k = 0; k < FEAT_DIM; k += 4) {
        float4 f = *(const float4*)&sFeat[w][k];
        acc = fmaf(f.x, sW[(k + 0) * EMBED_DIM + lane], acc);
        acc = fmaf(f.y, sW[(k + 1) * EMBED_DIM + lane], acc);
        acc = fmaf(f.z, sW[(k + 2) * EMBED_DIM + lane], acc);
        acc = fmaf(f.w, sW[(k + 3) * EMBED_DIM + lane], acc);
    }
    g_embed[n * EMBED_DIM + lane] = acc;   // coalesced 128B per node
    sE[w][lane] = acc;
    __syncwarp();

    if (lane < NC) {
        float a = 0.f;
        #pragma unroll
        for (int k = 0; k < EMBED_DIM; k++) {
            float e  = sE[w][k];
            float tt = fmaf(e, sW2[k][lane], sW1h[k][lane]);  // e*W2 + 0.5*W1
            a = fmaf(e, tt, a);                               // e^2*W2 + 0.5*e*W1
        }
        g_A[n * A_STRIDE + lane] = a;
    }
}

// ============================================================================
// Kernel B: per-edge logits / softmax / poss_edge / atomic segment-sum
// one thread per edge; edges read as int32 pairs
// ============================================================================
__global__ __launch_bounds__(256) void edge_kernel(
    const int2* __restrict__ edges, const float* __restrict__ weights,
    const float* __restrict__ Wtr, const float* __restrict__ btr,
    float* __restrict__ out_pe)
{
    __shared__ __align__(16) unsigned long long sW2p[NC][16]; // -2*W2, f32x2 packed
    __shared__ float sB[NC];
    __shared__ __align__(16) float sPE[256 * NC];  // staging for coalesced writeout

    const int t = threadIdx.x;
    for (int i = t; i < NC * 16; i += 256) {
        int c = i >> 4, k2 = i & 15;
        float lo = -2.f * Wtr[(EMBED_DIM + 2 * k2    ) * NC + c];
        float hi = -2.f * Wtr[(EMBED_DIM + 2 * k2 + 1) * NC + c];
        sW2p[c][k2] = pk2(lo, hi);
    }
    if (t < NC) sB[t] = btr[t];
    __syncthreads();

    const int e = blockIdx.x * 256 + t;
    const int2 sd = edges[e];
    const int s = sd.x, d = sd.y;
    const float wgt = weights[e];

    // base[c] = A_s[c] + A_d[c]  (bias added later)
    float base[20];
    {
        const float4* As = (const float4*)(g_A + (size_t)s * A_STRIDE);
        const float4* Ad = (const float4*)(g_A + (size_t)d * A_STRIDE);
        #pragma unroll
        for (int i = 0; i < 5; i++) {
            float4 a = As[i], b4 = Ad[i];
            base[4 * i + 0] = a.x + b4.x;
            base[4 * i + 1] = a.y + b4.y;
            base[4 * i + 2] = a.z + b4.z;
            base[4 * i + 3] = a.w + b4.w;
        }
    }

    // p = s .* d, packed f32x2
    unsigned long long p2[16];
    {
        const float4* Es = (const float4*)(g_embed + (size_t)s * EMBED_DIM);
        const float4* Ed = (const float4*)(g_embed + (size_t)d * EMBED_DIM);
        #pragma unroll
        for (int i = 0; i < 8; i++) {
            float4 a = Es[i], b4 = Ed[i];
            p2[2 * i    ] = pk2(a.x * b4.x, a.y * b4.y);
            p2[2 * i + 1] = pk2(a.z * b4.z, a.w * b4.w);
        }
    }

    // logits: base + b - 2 * sum_k p_k * W2[k,c]
    float logit[NC];
    #pragma unroll
    for (int c = 0; c < NC; c++) {
        unsigned long long acc = 0ull;  // (0.f, 0.f)
        #pragma unroll
        for (int k2 = 0; k2 < 16; k2++)
            acc = fma2(p2[k2], sW2p[c][k2], acc);
        float lo, hi;
        upk2(acc, lo, hi);
        logit[c] = sB[c] + base[c] + lo + hi;
    }

    // softmax(17)
    float m = logit[0];
    #pragma unroll
    for (int c = 1; c < NC; c++) m = fmaxf(m, logit[c]);
    float sum = 0.f;
    #pragma unroll
    for (int c = 0; c < NC; c++) { logit[c] = __expf(logit[c] - m); sum += logit[c]; }
    const float inv = __fdividef(1.f, sum);
    #pragma unroll
    for (int c = 0; c < NC; c++) logit[c] *= inv;

    // stage poss_edge (stride-17 shared write: odd stride -> conflict-free)
    #pragma unroll
    for (int c = 0; c < NC; c++) sPE[t * NC + c] = logit[c];

    // segment-sum: value = poss_edge * weight, vector reductions into padded rows
    float* rp = g_recall + (size_t)s * R_STRIDE;
    asm volatile("red.global.add.v4.f32 [%0], {%1,%2,%3,%4};" ::
                 "l"(rp + 0),  "f"(logit[0]  * wgt), "f"(logit[1]  * wgt),
                               "f"(logit[2]  * wgt), "f"(logit[3]  * wgt));
    asm volatile("red.global.add.v4.f32 [%0], {%1,%2,%3,%4};" ::
                 "l"(rp + 4),  "f"(logit[4]  * wgt), "f"(logit[5]  * wgt),
                               "f"(logit[6]  * wgt), "f"(logit[7]  * wgt));
    asm volatile("red.global.add.v4.f32 [%0], {%1,%2,%3,%4};" ::
                 "l"(rp + 8),  "f"(logit[8]  * wgt), "f"(logit[9]  * wgt),
                               "f"(logit[10] * wgt), "f"(logit[11] * wgt));
    asm volatile("red.global.add.v4.f32 [%0], {%1,%2,%3,%4};" ::
                 "l"(rp + 12), "f"(logit[12] * wgt), "f"(logit[13] * wgt),
                               "f"(logit[14] * wgt), "f"(logit[15] * wgt));
    atomicAdd(rp + 16, logit[16] * wgt);

    __syncthreads();
    // coalesced float4 writeout of the whole block tile (256*17 floats)
    float4*       outv = (float4*)(out_pe + (size_t)blockIdx.x * 256 * NC);
    const float4* shv  = (const float4*)sPE;
    #pragma unroll
    for (int i = t; i < 256 * NC / 4; i += 256) outv[i] = shv[i];
}

// ============================================================================
// Kernel C: poss_node = recall / neighbours_sum ; emit recall_node
// ============================================================================
__global__ __launch_bounds__(256) void final_kernel(
    const float* __restrict__ ns, float* __restrict__ out_pn,
    float* __restrict__ out_rn)
{
    const int i = blockIdx.x * 256 + threadIdx.x;
    if (i >= N_NODES * NC) return;
    const int n = i / NC, c = i - n * NC;
    const float r = g_recall[n * R_STRIDE + c];
    out_rn[i] = r;
    out_pn[i] = r / ns[n];
}

// ============================================================================
extern "C" void kernel_launch(void* const* d_in, const int* in_sizes, int n_in,
                              void* d_out, int out_size)
{
    // Identify inputs by their (pairwise-distinct) element counts — removes
    // any dependence on metadata ordering.
    const void *p_feat = nullptr, *p_edges = nullptr, *p_w = nullptr,
               *p_ns = nullptr, *p_We = nullptr, *p_be = nullptr,
               *p_Wt = nullptr, *p_bt = nullptr;
    for (int i = 0; i < n_in; i++) {
        switch (in_sizes[i]) {
            case N_NODES * FEAT_DIM:      p_feat  = d_in[i]; break; // 12,800,000
            case N_EDGES * 2:             p_edges = d_in[i]; break; //  3,200,000
            case N_EDGES:                 p_w     = d_in[i]; break; //  1,600,000
            case N_NODES:                 p_ns    = d_in[i]; break; //    100,000
            case FEAT_DIM * EMBED_DIM:    p_We    = d_in[i]; break; //      4,096
            case EMBED_DIM:               p_be    = d_in[i]; break; //         32
            case 2 * EMBED_DIM * NC:      p_Wt    = d_in[i]; break; //      1,088
            case NC:                      p_bt    = d_in[i]; break; //         17
            default: break;
        }
    }

    const float* feat    = (const float*)p_feat;
    const int2*  edges   = (const int2*)p_edges;   // int64 downcast to int32 by harness
    const float* weights = (const float*)p_w;
    const float* ns      = (const float*)p_ns;
    const float* Wemb    = (const float*)p_We;
    const float* bemb    = (const float*)p_be;
    const float* Wtr     = (const float*)p_Wt;
    const float* btr     = (const float*)p_bt;

    float* out    = (float*)d_out;
    float* out_pn = out;                                              // [100000,17]
    float* out_pe = out + (size_t)N_NODES * NC;                       // [1.6M,17]
    float* out_rn = out + (size_t)N_NODES * NC + (size_t)N_EDGES * NC;// [100000,17]

    void* rp = nullptr;
    cudaGetSymbolAddress(&rp, g_recall);
    cudaMemsetAsync(rp, 0, (size_t)N_NODES * R_STRIDE * sizeof(float), 0);

    node_kernel<<<N_NODES / 8, 256>>>(feat, Wemb, bemb, Wtr);
    edge_kernel<<<N_EDGES / 256, 256>>>(edges, weights, Wtr, btr, out_pe);
    final_kernel<<<(N_NODES * NC + 255) / 256, 256>>>(ns, out_pn, out_rn);
}

// round 5
// speedup vs baseline: 1.1434x; 1.1434x over previous
#include <cuda_runtime.h>
#include <cstdint>

#define N_NODES   100000
#define N_EDGES   1600000
#define FEAT_DIM  128
#define EMBED_DIM 32
#define NC        17
#define A_STRIDE  32   // 128B rows: exactly one line, 16B aligned
#define R_STRIDE  20   // 80B rows: 16B aligned for red.v4
#define FT_PAD    257  // sFeatT column stride (conflict-free loads)
#define KT        16   // k-tile width

// -------- device scratch (allocation-free rule: static __device__ globals) ---
__device__ __align__(16) float g_embed[N_NODES * EMBED_DIM];   // 12.8 MB
__device__ __align__(16) float g_A[N_NODES * A_STRIDE];        // 12.8 MB (cols 17..31 stay 0)
__device__ __align__(16) float g_recall[N_NODES * R_STRIDE];   //  8.0 MB

// -------- f32x2 packed helpers ----------------------------------------------
__device__ __forceinline__ unsigned long long pk2(float lo, float hi) {
    unsigned long long r;
    asm("mov.b64 %0, {%1,%2};" : "=l"(r) : "f"(lo), "f"(hi));
    return r;
}
__device__ __forceinline__ void upk2(unsigned long long v, float& lo, float& hi) {
    asm("mov.b64 {%0,%1}, %2;" : "=f"(lo), "=f"(hi) : "l"(v));
}
__device__ __forceinline__ unsigned long long fma2(unsigned long long a,
                                                   unsigned long long b,
                                                   unsigned long long c) {
    unsigned long long d;
    asm("fma.rn.f32x2 %0, %1, %2, %3;" : "=l"(d) : "l"(a), "l"(b), "l"(c));
    return d;
}

// ============================================================================
// Kernel A (v3): one node per THREAD, W broadcast from shared, f32x2 math.
// Static smem only (~37 KB < 48 KB default): 16-wide k-tiles.
// ============================================================================
__global__ __launch_bounds__(256) void node_kernel(
    const float* __restrict__ feat, const float* __restrict__ Wemb,
    const float* __restrict__ bemb, const float* __restrict__ Wtr)
{
    __shared__ __align__(16) float sFeatT[KT * FT_PAD];        // 16.45 KB
    __shared__ __align__(16) float sW[FEAT_DIM * EMBED_DIM];   // 16 KB, [k][j]
    __shared__ __align__(16) unsigned long long sW1h2[EMBED_DIM][9]; // 0.5*W1 c-pairs
    __shared__ __align__(16) unsigned long long sW22[EMBED_DIM][9];  // W2 c-pairs
    __shared__ __align__(16) unsigned long long sB2[16];

    const int t = threadIdx.x;

    // ---- stage weights ----
    {
        const float4* W4  = (const float4*)Wemb;
        float4*       sW4 = (float4*)sW;
        #pragma unroll
        for (int i = t; i < FEAT_DIM * EMBED_DIM / 4; i += 256) sW4[i] = W4[i];
        for (int i = t; i < EMBED_DIM * 9; i += 256) {
            int k = i / 9, c2 = i % 9, c = 2 * c2;
            float l1 = (c     < NC) ? 0.5f * Wtr[k * NC + c]     : 0.f;
            float h1 = (c + 1 < NC) ? 0.5f * Wtr[k * NC + c + 1] : 0.f;
            float l2 = (c     < NC) ? Wtr[(EMBED_DIM + k) * NC + c]     : 0.f;
            float h2 = (c + 1 < NC) ? Wtr[(EMBED_DIM + k) * NC + c + 1] : 0.f;
            sW1h2[k][c2] = pk2(l1, h1);
            sW22[k][c2]  = pk2(l2, h2);
        }
        if (t < 16) sB2[t] = pk2(bemb[2 * t], bemb[2 * t + 1]);
    }
    __syncthreads();

    const int n0 = blockIdx.x * 256;
    const int n  = n0 + t;

    unsigned long long acc2[16];
    #pragma unroll
    for (int j2 = 0; j2 < 16; j2++) acc2[j2] = sB2[j2];

    // ---- main GEMM: 8 k-tiles of 16 ----
    for (int kt = 0; kt < FEAT_DIM / KT; kt++) {
        if (kt) __syncthreads();
        // cooperative transposed load: 4 threads per node row-segment, 64 nodes/pass
        const int kk = (t & 3) * 4;
        #pragma unroll
        for (int pass = 0; pass < 4; pass++) {
            int col = pass * 64 + (t >> 2);
            int nn  = n0 + col; if (nn >= N_NODES) nn = N_NODES - 1;
            float4 f = __ldg((const float4*)(feat + (size_t)nn * FEAT_DIM + kt * KT + kk));
            sFeatT[(kk + 0) * FT_PAD + col] = f.x;
            sFeatT[(kk + 1) * FT_PAD + col] = f.y;
            sFeatT[(kk + 2) * FT_PAD + col] = f.z;
            sFeatT[(kk + 3) * FT_PAD + col] = f.w;
        }
        __syncthreads();

        #pragma unroll
        for (int k = 0; k < KT; k++) {
            float e = sFeatT[k * FT_PAD + t];
            unsigned long long e2 = pk2(e, e);
            const ulonglong2* wr = (const ulonglong2*)&sW[(kt * KT + k) * EMBED_DIM];
            #pragma unroll
            for (int j4 = 0; j4 < 8; j4++) {
                ulonglong2 w = wr[j4];                       // LDS.128 broadcast
                acc2[2 * j4    ] = fma2(e2, w.x, acc2[2 * j4    ]);
                acc2[2 * j4 + 1] = fma2(e2, w.y, acc2[2 * j4 + 1]);
            }
        }
    }

    // ---- fused A epilogue (embed lives in acc2) ----
    unsigned long long accA[9];
    #pragma unroll
    for (int c2 = 0; c2 < 9; c2++) accA[c2] = 0ull;
    #pragma unroll
    for (int k2 = 0; k2 < 16; k2++) {
        float e0, e1; upk2(acc2[k2], e0, e1);
        unsigned long long ea = pk2(e0, e0), eb = pk2(e1, e1);
        #pragma unroll
        for (int c2 = 0; c2 < 9; c2++) {
            unsigned long long t0 = fma2(ea, sW22[2 * k2][c2],     sW1h2[2 * k2][c2]);
            accA[c2] = fma2(ea, t0, accA[c2]);
            unsigned long long t1 = fma2(eb, sW22[2 * k2 + 1][c2], sW1h2[2 * k2 + 1][c2]);
            accA[c2] = fma2(eb, t1, accA[c2]);
        }
    }

    // ---- stores ----
    if (n < N_NODES) {
        ulonglong2* eo = (ulonglong2*)(g_embed + (size_t)n * EMBED_DIM);
        #pragma unroll
        for (int i = 0; i < 8; i++)
            eo[i] = make_ulonglong2(acc2[2 * i], acc2[2 * i + 1]);
        unsigned long long* Ao = (unsigned long long*)(g_A + (size_t)n * A_STRIDE);
        #pragma unroll
        for (int c2 = 0; c2 < 8; c2++) Ao[c2] = accA[c2];
        float lo, hi; upk2(accA[8], lo, hi);
        ((float*)Ao)[16] = lo;
    }
}

// ============================================================================
// Kernel B: per-edge logits / softmax / poss_edge / atomic segment-sum
// ============================================================================
__global__ __launch_bounds__(256) void edge_kernel(
    const int2* __restrict__ edges, const float* __restrict__ weights,
    const float* __restrict__ Wtr, const float* __restrict__ btr,
    float* __restrict__ out_pe)
{
    __shared__ __align__(16) unsigned long long sW2p[NC][16]; // -2*W2, f32x2 packed
    __shared__ float sB[NC];
    __shared__ __align__(16) float sPE[256 * NC];  // staging for coalesced writeout

    const int t = threadIdx.x;
    for (int i = t; i < NC * 16; i += 256) {
        int c = i >> 4, k2 = i & 15;
        float lo = -2.f * Wtr[(EMBED_DIM + 2 * k2    ) * NC + c];
        float hi = -2.f * Wtr[(EMBED_DIM + 2 * k2 + 1) * NC + c];
        sW2p[c][k2] = pk2(lo, hi);
    }
    if (t < NC) sB[t] = btr[t];
    __syncthreads();

    const int e = blockIdx.x * 256 + t;
    const int2 sd = edges[e];
    const int s = sd.x, d = sd.y;
    const float wgt = weights[e];

    // base[c] = A_s[c] + A_d[c]
    float base[20];
    {
        const float4* As = (const float4*)(g_A + (size_t)s * A_STRIDE);
        const float4* Ad = (const float4*)(g_A + (size_t)d * A_STRIDE);
        #pragma unroll
        for (int i = 0; i < 5; i++) {
            float4 a = As[i], b4 = Ad[i];
            base[4 * i + 0] = a.x + b4.x;
            base[4 * i + 1] = a.y + b4.y;
            base[4 * i + 2] = a.z + b4.z;
            base[4 * i + 3] = a.w + b4.w;
        }
    }

    // p = s .* d, packed f32x2
    unsigned long long p2[16];
    {
        const float4* Es = (const float4*)(g_embed + (size_t)s * EMBED_DIM);
        const float4* Ed = (const float4*)(g_embed + (size_t)d * EMBED_DIM);
        #pragma unroll
        for (int i = 0; i < 8; i++) {
            float4 a = Es[i], b4 = Ed[i];
            p2[2 * i    ] = pk2(a.x * b4.x, a.y * b4.y);
            p2[2 * i + 1] = pk2(a.z * b4.z, a.w * b4.w);
        }
    }

    // logits
    float logit[NC];
    #pragma unroll
    for (int c = 0; c < NC; c++) {
        unsigned long long acc = 0ull;
        #pragma unroll
        for (int k2 = 0; k2 < 16; k2++)
            acc = fma2(p2[k2], sW2p[c][k2], acc);
        float lo, hi;
        upk2(acc, lo, hi);
        logit[c] = sB[c] + base[c] + lo + hi;
    }

    // softmax(17)
    float m = logit[0];
    #pragma unroll
    for (int c = 1; c < NC; c++) m = fmaxf(m, logit[c]);
    float sum = 0.f;
    #pragma unroll
    for (int c = 0; c < NC; c++) { logit[c] = __expf(logit[c] - m); sum += logit[c]; }
    const float inv = __fdividef(1.f, sum);
    #pragma unroll
    for (int c = 0; c < NC; c++) logit[c] *= inv;

    #pragma unroll
    for (int c = 0; c < NC; c++) sPE[t * NC + c] = logit[c];

    // segment-sum
    float* rp = g_recall + (size_t)s * R_STRIDE;
    asm volatile("red.global.add.v4.f32 [%0], {%1,%2,%3,%4};" ::
                 "l"(rp + 0),  "f"(logit[0]  * wgt), "f"(logit[1]  * wgt),
                               "f"(logit[2]  * wgt), "f"(logit[3]  * wgt));
    asm volatile("red.global.add.v4.f32 [%0], {%1,%2,%3,%4};" ::
                 "l"(rp + 4),  "f"(logit[4]  * wgt), "f"(logit[5]  * wgt),
                               "f"(logit[6]  * wgt), "f"(logit[7]  * wgt));
    asm volatile("red.global.add.v4.f32 [%0], {%1,%2,%3,%4};" ::
                 "l"(rp + 8),  "f"(logit[8]  * wgt), "f"(logit[9]  * wgt),
                               "f"(logit[10] * wgt), "f"(logit[11] * wgt));
    asm volatile("red.global.add.v4.f32 [%0], {%1,%2,%3,%4};" ::
                 "l"(rp + 12), "f"(logit[12] * wgt), "f"(logit[13] * wgt),
                               "f"(logit[14] * wgt), "f"(logit[15] * wgt));
    atomicAdd(rp + 16, logit[16] * wgt);

    __syncthreads();
    float4*       outv = (float4*)(out_pe + (size_t)blockIdx.x * 256 * NC);
    const float4* shv  = (const float4*)sPE;
    #pragma unroll
    for (int i = t; i < 256 * NC / 4; i += 256) outv[i] = shv[i];
}

// ============================================================================
// Kernel C: poss_node = recall / neighbours_sum ; emit recall_node
// ============================================================================
__global__ __launch_bounds__(256) void final_kernel(
    const float* __restrict__ ns, float* __restrict__ out_pn,
    float* __restrict__ out_rn)
{
    const int i = blockIdx.x * 256 + threadIdx.x;
    if (i >= N_NODES * NC) return;
    const int n = i / NC, c = i - n * NC;
    const float r = g_recall[n * R_STRIDE + c];
    out_rn[i] = r;
    out_pn[i] = r / ns[n];
}

// ============================================================================
extern "C" void kernel_launch(void* const* d_in, const int* in_sizes, int n_in,
                              void* d_out, int out_size)
{
    const void *p_feat = nullptr, *p_edges = nullptr, *p_w = nullptr,
               *p_ns = nullptr, *p_We = nullptr, *p_be = nullptr,
               *p_Wt = nullptr, *p_bt = nullptr;
    for (int i = 0; i < n_in; i++) {
        switch (in_sizes[i]) {
            case N_NODES * FEAT_DIM:      p_feat  = d_in[i]; break;
            case N_EDGES * 2:             p_edges = d_in[i]; break;
            case N_EDGES:                 p_w     = d_in[i]; break;
            case N_NODES:                 p_ns    = d_in[i]; break;
            case FEAT_DIM * EMBED_DIM:    p_We    = d_in[i]; break;
            case EMBED_DIM:               p_be    = d_in[i]; break;
            case 2 * EMBED_DIM * NC:      p_Wt    = d_in[i]; break;
            case NC:                      p_bt    = d_in[i]; break;
            default: break;
        }
    }

    const float* feat    = (const float*)p_feat;
    const int2*  edges   = (const int2*)p_edges;
    const float* weights = (const float*)p_w;
    const float* ns      = (const float*)p_ns;
    const float* Wemb    = (const float*)p_We;
    const float* bemb    = (const float*)p_be;
    const float* Wtr     = (const float*)p_Wt;
    const float* btr     = (const float*)p_bt;

    float* out    = (float*)d_out;
    float* out_pn = out;                                              // [100000,17]
    float* out_pe = out + (size_t)N_NODES * NC;                       // [1.6M,17]
    float* out_rn = out + (size_t)N_NODES * NC + (size_t)N_EDGES * NC;// [100000,17]

    void* rp = nullptr;
    cudaGetSymbolAddress(&rp, g_recall);
    cudaMemsetAsync(rp, 0, (size_t)N_NODES * R_STRIDE * sizeof(float), 0);

    node_kernel<<<(N_NODES + 255) / 256, 256>>>(feat, Wemb, bemb, Wtr);
    edge_kernel<<<N_EDGES / 256, 256>>>(edges, weights, Wtr, btr, out_pe);
    final_kernel<<<(N_NODES * NC + 255) / 256, 256>>>(ns, out_pn, out_rn);
}

// round 6
// speedup vs baseline: 1.5811x; 1.3828x over previous
#include <cuda_runtime.h>
#include <cstdint>

#define N_NODES   100000
#define N_EDGES   1600000
#define FEAT_DIM  128
#define EMBED_DIM 32
#define NC        17
#define A_STRIDE  32   // 128B rows
#define R_STRIDE  20   // 80B rows
#define FT_PAD    257
#define KT        16
#define P_PAD     33   // sP row stride (odd, 4-group conflict-free)
#define B_PAD     21   // sBase row stride (odd)

// -------- device scratch ----------------------------------------------------
__device__ __align__(16) float g_embed[N_NODES * EMBED_DIM];
__device__ __align__(16) float g_A[N_NODES * A_STRIDE];     // cols 17..31 zero
__device__ __align__(16) float g_recall[N_NODES * R_STRIDE];

// -------- f32x2 helpers -----------------------------------------------------
__device__ __forceinline__ unsigned long long pk2(float lo, float hi) {
    unsigned long long r;
    asm("mov.b64 %0, {%1,%2};" : "=l"(r) : "f"(lo), "f"(hi));
    return r;
}
__device__ __forceinline__ void upk2(unsigned long long v, float& lo, float& hi) {
    asm("mov.b64 {%0,%1}, %2;" : "=f"(lo), "=f"(hi) : "l"(v));
}
__device__ __forceinline__ unsigned long long fma2(unsigned long long a,
                                                   unsigned long long b,
                                                   unsigned long long c) {
    unsigned long long d;
    asm("fma.rn.f32x2 %0, %1, %2, %3;" : "=l"(d) : "l"(a), "l"(b), "l"(c));
    return d;
}

// ============================================================================
// Kernel A: one node per thread, broadcast W from shared, f32x2 math.
// ============================================================================
__global__ __launch_bounds__(256) void node_kernel(
    const float* __restrict__ feat, const float* __restrict__ Wemb,
    const float* __restrict__ bemb, const float* __restrict__ Wtr)
{
    __shared__ __align__(16) float sFeatT[KT * FT_PAD];
    __shared__ __align__(16) float sW[FEAT_DIM * EMBED_DIM];
    __shared__ __align__(16) unsigned long long sW1h2[EMBED_DIM][9];
    __shared__ __align__(16) unsigned long long sW22[EMBED_DIM][9];
    __shared__ __align__(16) unsigned long long sB2[16];

    const int t = threadIdx.x;
    {
        const float4* W4  = (const float4*)Wemb;
        float4*       sW4 = (float4*)sW;
        #pragma unroll
        for (int i = t; i < FEAT_DIM * EMBED_DIM / 4; i += 256) sW4[i] = W4[i];
        for (int i = t; i < EMBED_DIM * 9; i += 256) {
            int k = i / 9, c2 = i % 9, c = 2 * c2;
            float l1 = (c     < NC) ? 0.5f * Wtr[k * NC + c]     : 0.f;
            float h1 = (c + 1 < NC) ? 0.5f * Wtr[k * NC + c + 1] : 0.f;
            float l2 = (c     < NC) ? Wtr[(EMBED_DIM + k) * NC + c]     : 0.f;
            float h2 = (c + 1 < NC) ? Wtr[(EMBED_DIM + k) * NC + c + 1] : 0.f;
            sW1h2[k][c2] = pk2(l1, h1);
            sW22[k][c2]  = pk2(l2, h2);
        }
        if (t < 16) sB2[t] = pk2(bemb[2 * t], bemb[2 * t + 1]);
    }
    __syncthreads();

    const int n0 = blockIdx.x * 256;
    const int n  = n0 + t;

    unsigned long long acc2[16];
    #pragma unroll
    for (int j2 = 0; j2 < 16; j2++) acc2[j2] = sB2[j2];

    for (int kt = 0; kt < FEAT_DIM / KT; kt++) {
        if (kt) __syncthreads();
        const int kk = (t & 3) * 4;
        #pragma unroll
        for (int pass = 0; pass < 4; pass++) {
            int col = pass * 64 + (t >> 2);
            int nn  = n0 + col; if (nn >= N_NODES) nn = N_NODES - 1;
            float4 f = __ldg((const float4*)(feat + (size_t)nn * FEAT_DIM + kt * KT + kk));
            sFeatT[(kk + 0) * FT_PAD + col] = f.x;
            sFeatT[(kk + 1) * FT_PAD + col] = f.y;
            sFeatT[(kk + 2) * FT_PAD + col] = f.z;
            sFeatT[(kk + 3) * FT_PAD + col] = f.w;
        }
        __syncthreads();

        #pragma unroll
        for (int k = 0; k < KT; k++) {
            float e = sFeatT[k * FT_PAD + t];
            unsigned long long e2 = pk2(e, e);
            const ulonglong2* wr = (const ulonglong2*)&sW[(kt * KT + k) * EMBED_DIM];
            #pragma unroll
            for (int j4 = 0; j4 < 8; j4++) {
                ulonglong2 w = wr[j4];
                acc2[2 * j4    ] = fma2(e2, w.x, acc2[2 * j4    ]);
                acc2[2 * j4 + 1] = fma2(e2, w.y, acc2[2 * j4 + 1]);
            }
        }
    }

    unsigned long long accA[9];
    #pragma unroll
    for (int c2 = 0; c2 < 9; c2++) accA[c2] = 0ull;
    #pragma unroll
    for (int k2 = 0; k2 < 16; k2++) {
        float e0, e1; upk2(acc2[k2], e0, e1);
        unsigned long long ea = pk2(e0, e0), eb = pk2(e1, e1);
        #pragma unroll
        for (int c2 = 0; c2 < 9; c2++) {
            unsigned long long t0 = fma2(ea, sW22[2 * k2][c2],     sW1h2[2 * k2][c2]);
            accA[c2] = fma2(ea, t0, accA[c2]);
            unsigned long long t1 = fma2(eb, sW22[2 * k2 + 1][c2], sW1h2[2 * k2 + 1][c2]);
            accA[c2] = fma2(eb, t1, accA[c2]);
        }
    }

    if (n < N_NODES) {
        ulonglong2* eo = (ulonglong2*)(g_embed + (size_t)n * EMBED_DIM);
        #pragma unroll
        for (int i = 0; i < 8; i++)
            eo[i] = make_ulonglong2(acc2[2 * i], acc2[2 * i + 1]);
        unsigned long long* Ao = (unsigned long long*)(g_A + (size_t)n * A_STRIDE);
        #pragma unroll
        for (int c2 = 0; c2 < 8; c2++) Ao[c2] = accA[c2];
        float lo, hi; upk2(accA[8], lo, hi);
        ((float*)Ao)[16] = lo;
    }
}

// ============================================================================
// Kernel B (v2): warp-cooperative gather + cooperative RED segment-sum.
// 256 threads / 256 edges per block; per-warp smem regions, __syncwarp only.
// ============================================================================
__global__ __launch_bounds__(256) void edge_kernel(
    const int2* __restrict__ edges, const float* __restrict__ weights,
    const float* __restrict__ Wtr, const float* __restrict__ btr,
    float* __restrict__ out_pe)
{
    __shared__ __align__(16) unsigned long long sW2p[NC][16]; // -2*W2 packed
    __shared__ float sB[NC];
    __shared__ float sP[8][32 * P_PAD];     // p = e_s .* e_d   (33.8 KB)
    __shared__ float sBase[8][32 * B_PAD];  // A_s + A_d, later reused as poss_edge (21.5 KB)
    __shared__ int   sS[256];
    __shared__ float sWgt[256];

    const int t    = threadIdx.x;
    const int w    = t >> 5;
    const int lane = t & 31;

    for (int i = t; i < NC * 16; i += 256) {
        int c = i >> 4, k2 = i & 15;
        float lo = -2.f * Wtr[(EMBED_DIM + 2 * k2    ) * NC + c];
        float hi = -2.f * Wtr[(EMBED_DIM + 2 * k2 + 1) * NC + c];
        sW2p[c][k2] = pk2(lo, hi);
    }
    if (t < NC) sB[t] = btr[t];

    // own edge
    const int e_own = blockIdx.x * 256 + t;
    const int2 sd   = edges[e_own];
    sS[t]   = sd.x;
    sWgt[t] = weights[e_own];
    __syncthreads();  // covers sW2p/sB + sS/sWgt

    float* myP    = sP[w];
    float* myBase = sBase[w];
    const int wb  = w * 32;                // warp's first edge slot in block

    // ---- cooperative gather: 8 lanes per row (lane -> float4 #k4) ----------
    {
        const int sub = lane >> 3;         // 0..3: edge subgroup
        const int k4  = lane & 7;          // float4 index within row
        // d-indices: need them per-edge; fetch via edges (uniform per 8 lanes is
        // not available) -> reload from the shared copy of s and a shared d? we
        // stored only s; load d via edges again cooperatively:
        #pragma unroll
        for (int i = 0; i < 8; i++) {
            const int e  = i * 4 + sub;            // edge within warp tile
            const int ge = blockIdx.x * 256 + wb + e;
            const int2 ed = __ldg(&edges[ge]);     // L1/L2 hit, 1 line per 4 lanes grp
            const int srow = ed.x, drow = ed.y;
            // embed product
            float4 a = __ldg((const float4*)(g_embed + (size_t)srow * EMBED_DIM) + k4);
            float4 b = __ldg((const float4*)(g_embed + (size_t)drow * EMBED_DIM) + k4);
            float* pp = myP + e * P_PAD + 4 * k4;
            pp[0] = a.x * b.x; pp[1] = a.y * b.y; pp[2] = a.z * b.z; pp[3] = a.w * b.w;
            // A sum (only words 0..19)
            if (k4 < 5) {
                float4 c4 = __ldg((const float4*)(g_A + (size_t)srow * A_STRIDE) + k4);
                float4 d4 = __ldg((const float4*)(g_A + (size_t)drow * A_STRIDE) + k4);
                float* bb = myBase + e * B_PAD + 4 * k4;
                bb[0] = c4.x + d4.x; bb[1] = c4.y + d4.y;
                bb[2] = c4.z + d4.z;
                if (k4 < 4) bb[3] = c4.w + d4.w;   // word 19 only when k4<5; k4=4 -> words 16..18? no:
            }
        }
    }
    __syncwarp();

    // NOTE on base words: k4=4 stores words 16,17,18 and (k4<4 guard) skips 19.
    // Word 19 unused (only 0..16 consumed), words 17,18 are zeros from g_A.

    // ---- per-thread compute on own edge ------------------------------------
    float logit[NC];
    {
        unsigned long long p2[16];
        const float* pr = myP + lane * P_PAD;
        #pragma unroll
        for (int k2 = 0; k2 < 16; k2++) p2[k2] = pk2(pr[2 * k2], pr[2 * k2 + 1]);
        const float* br = myBase + lane * B_PAD;
        #pragma unroll
        for (int c = 0; c < NC; c++) {
            unsigned long long acc = 0ull;
            #pragma unroll
            for (int k2 = 0; k2 < 16; k2++)
                acc = fma2(p2[k2], sW2p[c][k2], acc);
            float lo, hi; upk2(acc, lo, hi);
            logit[c] = sB[c] + br[c] + lo + hi;
        }
    }

    float m = logit[0];
    #pragma unroll
    for (int c = 1; c < NC; c++) m = fmaxf(m, logit[c]);
    float sum = 0.f;
    #pragma unroll
    for (int c = 0; c < NC; c++) { logit[c] = __expf(logit[c] - m); sum += logit[c]; }
    const float inv = __fdividef(1.f, sum);
    #pragma unroll
    for (int c = 0; c < NC; c++) logit[c] *= inv;

    // reuse own sBase row as poss_edge staging (own row read is complete)
    {
        float* br = myBase + lane * B_PAD;
        #pragma unroll
        for (int c = 0; c < NC; c++) br[c] = logit[c];
    }
    __syncwarp();

    // ---- cooperative segment-sum RED: 544 = 17 iters x 32 lanes ------------
    #pragma unroll
    for (int j = 0; j < NC; j++) {
        const int idx = j * 32 + lane;      // 0..543
        const int e   = idx / NC;           // edge within warp tile
        const int c   = idx - e * NC;
        const float v = myBase[e * B_PAD + c] * sWgt[wb + e];
        float* addr = g_recall + (size_t)sS[wb + e] * R_STRIDE + c;
        asm volatile("red.global.add.f32 [%0], %1;" :: "l"(addr), "f"(v));
    }

    // ---- coalesced poss_edge writeout: 544 floats per warp -----------------
    float* outw = out_pe + (size_t)(blockIdx.x * 256 + wb) * NC;
    #pragma unroll
    for (int j = 0; j < NC; j++) {
        const int idx = j * 32 + lane;
        const int e   = idx / NC;
        const int c   = idx - e * NC;
        outw[idx] = myBase[e * B_PAD + c];
    }
}

// ============================================================================
// Kernel C: poss_node = recall / neighbours_sum ; emit recall_node
// ============================================================================
__global__ __launch_bounds__(256) void final_kernel(
    const float* __restrict__ ns, float* __restrict__ out_pn,
    float* __restrict__ out_rn)
{
    const int i = blockIdx.x * 256 + threadIdx.x;
    if (i >= N_NODES * NC) return;
    const int n = i / NC, c = i - n * NC;
    const float r = g_recall[n * R_STRIDE + c];
    out_rn[i] = r;
    out_pn[i] = r / ns[n];
}

// ============================================================================
extern "C" void kernel_launch(void* const* d_in, const int* in_sizes, int n_in,
                              void* d_out, int out_size)
{
    const void *p_feat = nullptr, *p_edges = nullptr, *p_w = nullptr,
               *p_ns = nullptr, *p_We = nullptr, *p_be = nullptr,
               *p_Wt = nullptr, *p_bt = nullptr;
    for (int i = 0; i < n_in; i++) {
        switch (in_sizes[i]) {
            case N_NODES * FEAT_DIM:      p_feat  = d_in[i]; break;
            case N_EDGES * 2:             p_edges = d_in[i]; break;
            case N_EDGES:                 p_w     = d_in[i]; break;
            case N_NODES:                 p_ns    = d_in[i]; break;
            case FEAT_DIM * EMBED_DIM:    p_We    = d_in[i]; break;
            case EMBED_DIM:               p_be    = d_in[i]; break;
            case 2 * EMBED_DIM * NC:      p_Wt    = d_in[i]; break;
            case NC:                      p_bt    = d_in[i]; break;
            default: break;
        }
    }

    const float* feat    = (const float*)p_feat;
    const int2*  edges   = (const int2*)p_edges;
    const float* weights = (const float*)p_w;
    const float* ns      = (const float*)p_ns;
    const float* Wemb    = (const float*)p_We;
    const float* bemb    = (const float*)p_be;
    const float* Wtr     = (const float*)p_Wt;
    const float* btr     = (const float*)p_bt;

    float* out    = (float*)d_out;
    float* out_pn = out;
    float* out_pe = out + (size_t)N_NODES * NC;
    float* out_rn = out + (size_t)N_NODES * NC + (size_t)N_EDGES * NC;

    void* rp = nullptr;
    cudaGetSymbolAddress(&rp, g_recall);
    cudaMemsetAsync(rp, 0, (size_t)N_NODES * R_STRIDE * sizeof(float), 0);

    node_kernel<<<(N_NODES + 255) / 256, 256>>>(feat, Wemb, bemb, Wtr);
    edge_kernel<<<N_EDGES / 256, 256>>>(edges, weights, Wtr, btr, out_pe);
    final_kernel<<<(N_NODES * NC + 255) / 256, 256>>>(ns, out_pn, out_rn);
}